// round 1
// baseline (speedup 1.0000x reference)
#include <cuda_runtime.h>

#define N_NODES 50000
#define N_RELS  8
#define IN_DIM  128
#define OUT_DIM 128
#define N_EDGES 800000

// Scratch (allocation-free rule: __device__ globals)
__device__ float g_h[(size_t)N_RELS * N_NODES * OUT_DIM];   // 204.8 MB: h[r][n][o]
__device__ float g_counts[N_RELS * N_NODES];                // 1.6 MB

// ---------------------------------------------------------------------------
// Kernel 1: out = bias (broadcast), counts = 0
// ---------------------------------------------------------------------------
__global__ void init_kernel(float* __restrict__ out, const float* __restrict__ bias) {
    int idx = blockIdx.x * blockDim.x + threadIdx.x;
    int stride = gridDim.x * blockDim.x;
    const int total = N_NODES * OUT_DIM;
    for (int i = idx; i < total; i += stride)
        out[i] = bias[i & (OUT_DIM - 1)];
    for (int i = idx; i < N_RELS * N_NODES; i += stride)
        g_counts[i] = 0.0f;
}

// ---------------------------------------------------------------------------
// Kernel 2: counts[rel*N + tgt] += 1 per edge
// ---------------------------------------------------------------------------
__global__ void count_kernel(const int* __restrict__ triples) {
    int e = blockIdx.x * blockDim.x + threadIdx.x;
    if (e < N_EDGES) {
        int rel = triples[e * 3 + 1];
        int tgt = triples[e * 3 + 2];
        atomicAdd(&g_counts[rel * N_NODES + tgt], 1.0f);
    }
}

// ---------------------------------------------------------------------------
// Kernel 3: h[r] = features @ W[r]   (fp32 SGEMM, 128x128 tile, 8x8 microtile)
//   A = features [N, 128] row-major, B = W[r] [128, 128] row-major (i,o)
// ---------------------------------------------------------------------------
__global__ __launch_bounds__(256)
void gemm_kernel(const float* __restrict__ A, const float* __restrict__ W) {
    const int r  = blockIdx.y;
    const int m0 = blockIdx.x * 128;
    const float* B = W + (size_t)r * IN_DIM * OUT_DIM;
    float* H = g_h + (size_t)r * N_NODES * OUT_DIM;

    __shared__ float As[16][128];   // k-major (transposed on store)
    __shared__ float Bs[16][128];

    const int tid = threadIdx.x;
    const int tx = tid & 15;        // output-col group (8 cols)
    const int ty = tid >> 4;        // output-row group (8 rows)

    float acc[8][8];
#pragma unroll
    for (int i = 0; i < 8; i++)
#pragma unroll
        for (int j = 0; j < 8; j++) acc[i][j] = 0.0f;

    // A-chunk load mapping: thread -> (row = tid>>1, 8 k's at (tid&1)*8)
    const int arow  = tid >> 1;
    const int apart = (tid & 1) * 8;
    const int grow  = m0 + arow;
    const bool avalid = (grow < N_NODES);
    const float* Arow = A + (size_t)(avalid ? grow : 0) * IN_DIM;

    // B-chunk load mapping: float4 idx = tid (rows 0..7) and tid+256 (rows 8..15)
    const int brow = tid >> 5;       // 0..7
    const int bcol = (tid & 31) * 4; // 0..124

#pragma unroll 1
    for (int k0 = 0; k0 < IN_DIM; k0 += 16) {
        float4 a0 = make_float4(0.f, 0.f, 0.f, 0.f);
        float4 a1 = a0;
        if (avalid) {
            a0 = *(const float4*)(Arow + k0 + apart);
            a1 = *(const float4*)(Arow + k0 + apart + 4);
        }
        float4 b0 = *(const float4*)(B + (size_t)(k0 + brow)     * OUT_DIM + bcol);
        float4 b1 = *(const float4*)(B + (size_t)(k0 + 8 + brow) * OUT_DIM + bcol);

        __syncthreads();
        As[apart + 0][arow] = a0.x;  As[apart + 1][arow] = a0.y;
        As[apart + 2][arow] = a0.z;  As[apart + 3][arow] = a0.w;
        As[apart + 4][arow] = a1.x;  As[apart + 5][arow] = a1.y;
        As[apart + 6][arow] = a1.z;  As[apart + 7][arow] = a1.w;
        *(float4*)&Bs[brow][bcol]     = b0;
        *(float4*)&Bs[brow + 8][bcol] = b1;
        __syncthreads();

#pragma unroll
        for (int kk = 0; kk < 16; kk++) {
            float a[8], b[8];
            *(float4*)(a)     = *(const float4*)&As[kk][ty * 8];
            *(float4*)(a + 4) = *(const float4*)&As[kk][ty * 8 + 4];
            *(float4*)(b)     = *(const float4*)&Bs[kk][tx * 8];
            *(float4*)(b + 4) = *(const float4*)&Bs[kk][tx * 8 + 4];
#pragma unroll
            for (int i = 0; i < 8; i++)
#pragma unroll
                for (int j = 0; j < 8; j++)
                    acc[i][j] += a[i] * b[j];
        }
    }

#pragma unroll
    for (int i = 0; i < 8; i++) {
        int row = m0 + ty * 8 + i;
        if (row < N_NODES) {
            float* Hp = H + (size_t)row * OUT_DIM + tx * 8;
            *(float4*)(Hp)     = make_float4(acc[i][0], acc[i][1], acc[i][2], acc[i][3]);
            *(float4*)(Hp + 4) = make_float4(acc[i][4], acc[i][5], acc[i][6], acc[i][7]);
        }
    }
}

// ---------------------------------------------------------------------------
// Kernel 4: one warp per edge: out[tgt] += h[rel,src] / counts[rel*N+tgt]
// ---------------------------------------------------------------------------
__global__ void edge_kernel(const int* __restrict__ triples, float* __restrict__ out) {
    int warp = (blockIdx.x * blockDim.x + threadIdx.x) >> 5;
    int lane = threadIdx.x & 31;
    if (warp >= N_EDGES) return;

    int src = triples[warp * 3 + 0];
    int rel = triples[warp * 3 + 1];
    int tgt = triples[warp * 3 + 2];

    float val = 1.0f / g_counts[rel * N_NODES + tgt];

    const float4* h4 = (const float4*)(g_h + ((size_t)rel * N_NODES + src) * OUT_DIM);
    float4 v = h4[lane];
    v.x *= val; v.y *= val; v.z *= val; v.w *= val;

    float4* o = (float4*)(out + (size_t)tgt * OUT_DIM) + lane;
    asm volatile("red.global.add.v4.f32 [%0], {%1, %2, %3, %4};"
                 :: "l"(o), "f"(v.x), "f"(v.y), "f"(v.z), "f"(v.w) : "memory");
}

// ---------------------------------------------------------------------------
extern "C" void kernel_launch(void* const* d_in, const int* in_sizes, int n_in,
                              void* d_out, int out_size) {
    const int*   triples  = (const int*)d_in[0];    // [E, 3] int32 (src, rel, tgt)
    const float* features = (const float*)d_in[1];  // [N, 128]
    const float* weights  = (const float*)d_in[2];  // [8, 128, 128]
    const float* bias     = (const float*)d_in[3];  // [128]
    float* out = (float*)d_out;                     // [N, 128]

    (void)in_sizes; (void)n_in; (void)out_size;

    init_kernel<<<1024, 256>>>(out, bias);
    count_kernel<<<(N_EDGES + 255) / 256, 256>>>(triples);

    dim3 gg((N_NODES + 127) / 128, N_RELS);
    gemm_kernel<<<gg, 256>>>(features, weights);

    // 1 warp per edge, 8 warps per block
    edge_kernel<<<(N_EDGES + 7) / 8, 256>>>(triples, out);
}

// round 3
// speedup vs baseline: 2.2983x; 2.2983x over previous
#include <cuda_runtime.h>
#include <cuda_bf16.h>
#include <cstdint>

#define N_NODES 50000
#define N_RELS  8
#define IN_DIM  128
#define OUT_DIM 128
#define N_EDGES 800000
#define M_TILES ((N_NODES + 127) / 128)   // 391

// Scratch (__device__ globals: allocation-free rule)
__device__ __align__(16) float g_h[(size_t)N_RELS * N_NODES * OUT_DIM]; // 204.8 MB
__device__ float g_counts[N_RELS * N_NODES];                            // 1.6 MB
__device__ __align__(16) __nv_bfloat16 g_wt_hi[N_RELS * 128 * 128];     // W^T hi [r][o][k]
__device__ __align__(16) __nv_bfloat16 g_wt_lo[N_RELS * 128 * 128];     // W^T lo [r][o][k]

// ---------------------------------------------------------------------------
// warp-mma helpers (baseline PTX ISA — works on plain sm_103 target)
// ---------------------------------------------------------------------------
__device__ __forceinline__ uint32_t smem_u32(const void* p) {
    uint32_t a;
    asm("{ .reg .u64 t; cvta.to.shared.u64 t, %1; cvt.u32.u64 %0, t; }"
        : "=r"(a) : "l"(p));
    return a;
}

__device__ __forceinline__ void ldsm4(uint32_t* r, uint32_t addr) {
    asm volatile("ldmatrix.sync.aligned.m8n8.x4.shared.b16 {%0,%1,%2,%3}, [%4];"
                 : "=r"(r[0]), "=r"(r[1]), "=r"(r[2]), "=r"(r[3]) : "r"(addr));
}

__device__ __forceinline__ void mma_bf16(float* d, const uint32_t* a, const uint32_t* b) {
    asm volatile(
        "mma.sync.aligned.m16n8k16.row.col.f32.bf16.bf16.f32 "
        "{%0,%1,%2,%3}, {%4,%5,%6,%7}, {%8,%9}, {%0,%1,%2,%3};"
        : "+f"(d[0]), "+f"(d[1]), "+f"(d[2]), "+f"(d[3])
        : "r"(a[0]), "r"(a[1]), "r"(a[2]), "r"(a[3]), "r"(b[0]), "r"(b[1]));
}

// smem tile: 128 rows x 256B (128 bf16). 16 chunks of 16B per row.
// swizzle: chunk' = chunk ^ (row & 7)  -> conflict-free ldmatrix + fills.
__device__ __forceinline__ uint32_t sw_off(int row, int chunk) {
    return (uint32_t)(row * 256 + ((chunk ^ (row & 7)) << 4));
}

// SMEM layout (dynamic): Ahi | Alo | Bhi | Blo, 32KB each
#define SM_AH 0
#define SM_AL 32768
#define SM_BH 65536
#define SM_BL 98304
#define SMEM_TOTAL 131072

// ---------------------------------------------------------------------------
// Kernel 1: out = bias, counts = 0
// ---------------------------------------------------------------------------
__global__ void init_kernel(float* __restrict__ out, const float* __restrict__ bias) {
    int idx = blockIdx.x * blockDim.x + threadIdx.x;
    int stride = gridDim.x * blockDim.x;
    const int total = N_NODES * OUT_DIM;
    for (int i = idx; i < total; i += stride)
        out[i] = bias[i & (OUT_DIM - 1)];
    for (int i = idx; i < N_RELS * N_NODES; i += stride)
        g_counts[i] = 0.0f;
}

// ---------------------------------------------------------------------------
// Kernel 2: counts[rel*N + tgt] += 1
// ---------------------------------------------------------------------------
__global__ void count_kernel(const int* __restrict__ triples) {
    int e = blockIdx.x * blockDim.x + threadIdx.x;
    if (e < N_EDGES) {
        int rel = triples[e * 3 + 1];
        int tgt = triples[e * 3 + 2];
        atomicAdd(&g_counts[rel * N_NODES + tgt], 1.0f);
    }
}

// ---------------------------------------------------------------------------
// Kernel 2b: W [r][k][o] fp32 -> Wt hi/lo [r][o][k] bf16 (transpose + split)
// ---------------------------------------------------------------------------
__global__ void split_w_kernel(const float* __restrict__ W) {
    int idx = blockIdx.x * blockDim.x + threadIdx.x;
    if (idx >= N_RELS * 128 * 128) return;
    int r = idx >> 14;
    int k = (idx >> 7) & 127;
    int o = idx & 127;
    float x = W[idx];
    __nv_bfloat16 hi = __float2bfloat16(x);
    __nv_bfloat16 lo = __float2bfloat16(x - __bfloat162float(hi));
    int dst = (r << 14) + (o << 7) + k;
    g_wt_hi[dst] = hi;
    g_wt_lo[dst] = lo;
}

// ---------------------------------------------------------------------------
// Kernel 3: split-bf16 GEMM via mma.sync: h[r] = features @ W[r]
//   CTA = 128x128 output tile for one relation; full K=128 resident in smem.
//   8 warps, each 32x64 output; 8 k-steps x (Ahi*Bhi + Ahi*Blo + Alo*Bhi).
// ---------------------------------------------------------------------------
__global__ void __launch_bounds__(256, 1)
gemm_mma_kernel(const float* __restrict__ A) {
    extern __shared__ char smem[];
    const int r  = blockIdx.y;
    const int m0 = blockIdx.x * 128;
    const int tid = threadIdx.x;
    const int wid = tid >> 5;
    const int lid = tid & 31;
    const uint32_t sb = smem_u32(smem);

    // ---- fill smem: A (convert fp32->bf16 hi/lo) and B (pre-split bf16) ----
    {
        const __nv_bfloat16* Bh = g_wt_hi + (r << 14);
        const __nv_bfloat16* Bl = g_wt_lo + (r << 14);
#pragma unroll
        for (int i = 0; i < 8; i++) {
            int cid = tid + i * 256;          // 2048 chunks
            int row = cid >> 4;
            int chunk = cid & 15;
            uint32_t so = sw_off(row, chunk);

            // B: row = o, chunk covers k [chunk*8, +8)
            *(uint4*)(smem + SM_BH + so) = *(const uint4*)(Bh + (row << 7) + (chunk << 3));
            *(uint4*)(smem + SM_BL + so) = *(const uint4*)(Bl + (row << 7) + (chunk << 3));

            // A: row = m, convert 8 fp32 -> hi/lo bf16
            int grow = m0 + row;
            if (grow >= N_NODES) grow = 0;    // junk rows, epilogue guards
            const float* p = A + ((size_t)grow << 7) + (chunk << 3);
            float4 x0 = *(const float4*)p;
            float4 x1 = *(const float4*)(p + 4);
            float f[8] = {x0.x, x0.y, x0.z, x0.w, x1.x, x1.y, x1.z, x1.w};
            uint32_t ph[4], pl[4];
#pragma unroll
            for (int j = 0; j < 4; j++) {
                __nv_bfloat162 th, tl;
                float a = f[2 * j], b = f[2 * j + 1];
                th.x = __float2bfloat16(a);
                th.y = __float2bfloat16(b);
                tl.x = __float2bfloat16(a - __bfloat162float(th.x));
                tl.y = __float2bfloat16(b - __bfloat162float(th.y));
                ph[j] = *reinterpret_cast<uint32_t*>(&th);
                pl[j] = *reinterpret_cast<uint32_t*>(&tl);
            }
            *(uint4*)(smem + SM_AH + so) = make_uint4(ph[0], ph[1], ph[2], ph[3]);
            *(uint4*)(smem + SM_AL + so) = make_uint4(pl[0], pl[1], pl[2], pl[3]);
        }
    }
    __syncthreads();

    // ---- per-lane ldmatrix base addresses ----
    // A (16x16 x4): row = wm*32 + (lid&15) [+16 for tile 1], chunk = s*2 + (lid>>4)
    const int wm = wid & 3;          // warp m-tile (32 rows)
    const int wn = wid >> 2;         // warp n-tile (64 cols)
    const int a_row  = wm * 32 + (lid & 15);
    const int a_kc   = lid >> 4;                 // 0/1
    const int a_and  = a_row & 7;
    const uint32_t a_base = sb + (uint32_t)(a_row * 256);
    // B (16n x 16k x4): n_row = wn*64 + g*16 + ((lid>>4)<<3) + (lid&7), chunk = s*2 + ((lid>>3)&1)
    const int b_row  = wn * 64 + ((lid >> 4) << 3) + (lid & 7);
    const int b_kc   = (lid >> 3) & 1;
    const int b_and  = b_row & 7;    // invariant under +16*g
    const uint32_t b_base = sb + (uint32_t)(b_row * 256);

    float acc[2][8][4];
#pragma unroll
    for (int mt = 0; mt < 2; mt++)
#pragma unroll
        for (int nn = 0; nn < 8; nn++)
#pragma unroll
            for (int c = 0; c < 4; c++) acc[mt][nn][c] = 0.0f;

#pragma unroll
    for (int s = 0; s < 8; s++) {
        uint32_t Ah[2][4], Al[2][4], Bh[4][4], Bl[4][4];
        const uint32_t ac = (uint32_t)(((s * 2 + a_kc) ^ a_and) << 4);
        const uint32_t bc = (uint32_t)(((s * 2 + b_kc) ^ b_and) << 4);
#pragma unroll
        for (int t = 0; t < 2; t++) {
            ldsm4(Ah[t], a_base + SM_AH + t * 4096 + ac);
            ldsm4(Al[t], a_base + SM_AL + t * 4096 + ac);
        }
#pragma unroll
        for (int g = 0; g < 4; g++) {
            ldsm4(Bh[g], b_base + SM_BH + g * 4096 + bc);
            ldsm4(Bl[g], b_base + SM_BL + g * 4096 + bc);
        }
#pragma unroll
        for (int g = 0; g < 4; g++) {
#pragma unroll
            for (int half = 0; half < 2; half++) {
                const int nn = g * 2 + half;
                const uint32_t* bh = &Bh[g][half * 2];
                const uint32_t* bl = &Bl[g][half * 2];
#pragma unroll
                for (int mt = 0; mt < 2; mt++) {
                    mma_bf16(acc[mt][nn], Ah[mt], bh);   // Ahi*Bhi
                    mma_bf16(acc[mt][nn], Ah[mt], bl);   // Ahi*Blo
                    mma_bf16(acc[mt][nn], Al[mt], bh);   // Alo*Bhi
                }
            }
        }
    }

    // ---- epilogue: write fp32 h ----
    float* H = g_h + ((size_t)r * N_NODES << 7);
    const int col0 = wn * 64 + (lid & 3) * 2;
#pragma unroll
    for (int mt = 0; mt < 2; mt++) {
        int row = m0 + wm * 32 + mt * 16 + (lid >> 2);
        if (row < N_NODES) {
            float* Hp = H + ((size_t)row << 7) + col0;
#pragma unroll
            for (int nn = 0; nn < 8; nn++)
                *(float2*)(Hp + nn * 8) = make_float2(acc[mt][nn][0], acc[mt][nn][1]);
        }
        if (row + 8 < N_NODES) {
            float* Hp = H + ((size_t)(row + 8) << 7) + col0;
#pragma unroll
            for (int nn = 0; nn < 8; nn++)
                *(float2*)(Hp + nn * 8) = make_float2(acc[mt][nn][2], acc[mt][nn][3]);
        }
    }
}

// ---------------------------------------------------------------------------
// Kernel 4: 8 lanes per edge, 4 independent float4 gathers per lane (MLP=4)
//   out[tgt] += h[rel,src] / counts[rel*N+tgt]
// ---------------------------------------------------------------------------
__global__ void edge_kernel(const int* __restrict__ triples, float* __restrict__ out) {
    int t = blockIdx.x * blockDim.x + threadIdx.x;
    int e = t >> 3;
    int p = t & 7;
    if (e >= N_EDGES) return;

    int src = triples[e * 3 + 0];
    int rel = triples[e * 3 + 1];
    int tgt = triples[e * 3 + 2];

    float val = 1.0f / g_counts[rel * N_NODES + tgt];

    const float4* h4 = (const float4*)(g_h + (((size_t)rel * N_NODES + src) << 7)) + p * 4;
    float4 v0 = h4[0];
    float4 v1 = h4[1];
    float4 v2 = h4[2];
    float4 v3 = h4[3];
    v0.x *= val; v0.y *= val; v0.z *= val; v0.w *= val;
    v1.x *= val; v1.y *= val; v1.z *= val; v1.w *= val;
    v2.x *= val; v2.y *= val; v2.z *= val; v2.w *= val;
    v3.x *= val; v3.y *= val; v3.z *= val; v3.w *= val;

    float4* o = (float4*)(out + ((size_t)tgt << 7)) + p * 4;
    asm volatile("red.global.add.v4.f32 [%0], {%1, %2, %3, %4};"
                 :: "l"(o + 0), "f"(v0.x), "f"(v0.y), "f"(v0.z), "f"(v0.w) : "memory");
    asm volatile("red.global.add.v4.f32 [%0], {%1, %2, %3, %4};"
                 :: "l"(o + 1), "f"(v1.x), "f"(v1.y), "f"(v1.z), "f"(v1.w) : "memory");
    asm volatile("red.global.add.v4.f32 [%0], {%1, %2, %3, %4};"
                 :: "l"(o + 2), "f"(v2.x), "f"(v2.y), "f"(v2.z), "f"(v2.w) : "memory");
    asm volatile("red.global.add.v4.f32 [%0], {%1, %2, %3, %4};"
                 :: "l"(o + 3), "f"(v3.x), "f"(v3.y), "f"(v3.z), "f"(v3.w) : "memory");
}

// ---------------------------------------------------------------------------
extern "C" void kernel_launch(void* const* d_in, const int* in_sizes, int n_in,
                              void* d_out, int out_size) {
    const int*   triples  = (const int*)d_in[0];    // [E, 3] (src, rel, tgt)
    const float* features = (const float*)d_in[1];  // [N, 128]
    const float* weights  = (const float*)d_in[2];  // [8, 128, 128]
    const float* bias     = (const float*)d_in[3];  // [128]
    float* out = (float*)d_out;                     // [N, 128]
    (void)in_sizes; (void)n_in; (void)out_size;

    cudaFuncSetAttribute(gemm_mma_kernel,
                         cudaFuncAttributeMaxDynamicSharedMemorySize, SMEM_TOTAL);

    init_kernel<<<1024, 256>>>(out, bias);
    count_kernel<<<(N_EDGES + 255) / 256, 256>>>(triples);
    split_w_kernel<<<(N_RELS * 128 * 128 + 255) / 256, 256>>>(weights);

    dim3 gg(M_TILES, N_RELS);
    gemm_mma_kernel<<<gg, 256, SMEM_TOTAL>>>(features);

    edge_kernel<<<(N_EDGES * 8 + 255) / 256, 256>>>(triples, out);
}